// round 14
// baseline (speedup 1.0000x reference)
#include <cuda_runtime.h>
#include <cuda_bf16.h>
#include <cuda_fp16.h>
#include <math.h>
#include <cstdint>

// Problem constants
#define B 8
#define N 2048
#define D 256
#define BN (B*N)           // 16384 rows
#define BD (B*D)           // 2048

// ---------------- scratch (__device__ globals; no allocations allowed) ----------
__device__ __half g_qh[(size_t)BN * 256];         // 8.4 MB: fp16 of proj (adj GEMM input)
__device__ __half g_xq[(size_t)BN * 256];         // 8.4 MB: fp16 of x
__device__ __half g_wq[256 * 256];                // fp16 of W_fp^T (row e, col d)
__device__ float g_ss[BN];           // sum proj^2 per row (atomic)
__device__ float g_dt[BN];           // proj . w_s per row (atomic)
__device__ float g_deg[BN];          // row sums of adj (atomic)
__device__ float g_w[BN];            // w[m] = sum_i adj[m,i]/deg[i] (atomic)
__device__ float g_xpart[32 * BD];   // partial sums of x over n (32 chunks)
__device__ float g_rpart[32 * BD];   // partial sums of w*proj over m (32 chunks)

// ======================= helpers (arch-agnostic PTX only) ==========================
__device__ __forceinline__ uint32_t smem_to_u32(const void* smem_ptr) {
    uint32_t addr;
    asm("{ .reg .u64 tmp; cvta.to.shared.u64 tmp, %1; cvt.u32.u64 %0, tmp; }"
        : "=r"(addr) : "l"(smem_ptr));
    return addr;
}
template<int NG>
__device__ __forceinline__ void cp_async_wait() {
    asm volatile("cp.async.wait_group %0;" :: "n"(NG));
}
__device__ __forceinline__ void cp_async16(uint32_t dst, const void* src) {
    asm volatile("cp.async.cg.shared.global [%0], [%1], 16;" :: "r"(dst), "l"(src));
}
__device__ __forceinline__ void cp_async_commit() {
    asm volatile("cp.async.commit_group;" ::: "memory");
}
__device__ __forceinline__ void ldmatrix_x4(uint32_t& r0, uint32_t& r1,
                                            uint32_t& r2, uint32_t& r3, uint32_t addr) {
    asm volatile("ldmatrix.sync.aligned.m8n8.x4.shared.b16 {%0,%1,%2,%3}, [%4];"
                 : "=r"(r0), "=r"(r1), "=r"(r2), "=r"(r3) : "r"(addr));
}
__device__ __forceinline__ void mma_f16(float* c, const uint32_t* a, const uint32_t* b) {
    asm volatile(
        "mma.sync.aligned.m16n8k16.row.col.f32.f16.f16.f32 "
        "{%0,%1,%2,%3}, {%4,%5,%6,%7}, {%8,%9}, {%0,%1,%2,%3};"
        : "+f"(c[0]), "+f"(c[1]), "+f"(c[2]), "+f"(c[3])
        : "r"(a[0]), "r"(a[1]), "r"(a[2]), "r"(a[3]), "r"(b[0]), "r"(b[1]));
}

#define TPAD 80
#define TILE_BYTES (128 * TPAD)     // 10240
#define NBUF 4
#define NSTEP 8
#define MMA_BUF_BYTES (NBUF * TILE_BYTES * 2)      // 81920 (stage 128x132 fp32 fits)
#define ADJ_SMEM (MMA_BUF_BYTES + 6 * 128 * 4)     // + rI,sI,rM,sM,sdeg,sdegM
#define PROJ_SMEM (MMA_BUF_BYTES + 1024)           // + bias[128] + ws[128]

// ---------------- K-splitx: fp16 of x + partial xsum; fp16 of W^T; zero accums -----
__global__ void k_splitx(const float* __restrict__ x, const float* __restrict__ W) {
    const int blk = blockIdx.x;
    const int d = threadIdx.x;
    if (blk < 256) {
        const int b = blk >> 5;            // 32 chunks per batch
        const int n0 = (blk & 31) * 64;
        const float* X = x + (size_t)(b * N + n0) * D;
        __half* Q = g_xq + (size_t)(b * N + n0) * 256;
        float acc = 0.f;
#pragma unroll 8
        for (int n = 0; n < 64; n++) {
            float v = X[n * D + d];
            acc += v;
            Q[n * 256 + d] = __float2half(v);
        }
        g_xpart[(blk & 31) * BD + b * D + d] = acc;
    } else if (blk < 260) {
        const int base = (blk - 256) * 16384;
        for (int i = 0; i < 64; i++) {
            int j = base + i * 256 + d;
            int e = j >> 8, dd = j & 255;
            g_wq[e * 256 + dd] = __float2half(W[dd * D + e]);
        }
    } else {
        int t = (blk - 260) * 256 + d;     // 64 blocks cover BN
        g_ss[t] = 0.f; g_dt[t] = 0.f; g_deg[t] = 0.f; g_w[t] = 0.f;
    }
}

// ---------------- K1: proj GEMM on tensor cores (fp16, K=256) + row stats ----------
__global__ void __launch_bounds__(256, 2) k_proj_mma(const float* __restrict__ bias,
                                                     const float* __restrict__ ws) {
    extern __shared__ __align__(16) char dynsm[];
    char* smA = dynsm;
    char* smB = dynsm + NBUF * TILE_BYTES;
    float* bsh = (float*)(dynsm + MMA_BUF_BYTES);
    float* wsm = bsh + 128;

    const int tid = threadIdx.x;
    const int lane = tid & 31, w = tid >> 5;
    const int i0 = blockIdx.x * 128;
    const int e0 = blockIdx.y * 128;

    if (tid < 128) { bsh[tid] = bias[e0 + tid]; wsm[tid] = ws[e0 + tid]; }

    const __half* QA = g_xq + (size_t)i0 * 256;
    const __half* QB = g_wq + (size_t)e0 * 256;
    const uint32_t aBase = smem_to_u32(smA);
    const uint32_t bBase = smem_to_u32(smB);

    const int r0c = (tid + 0)   >> 2, c0c = (tid + 0)   & 3;
    const int r1c = (tid + 256) >> 2, c1c = (tid + 256) & 3;

    auto load_chunk = [&](int s, int buf) {
        int kb = s * 32;
        uint32_t aB = aBase + buf * TILE_BYTES;
        uint32_t bB = bBase + buf * TILE_BYTES;
        cp_async16(aB + r0c * TPAD + c0c * 16, QA + (size_t)r0c * 256 + kb + c0c * 8);
        cp_async16(aB + r1c * TPAD + c1c * 16, QA + (size_t)r1c * 256 + kb + c1c * 8);
        cp_async16(bB + r0c * TPAD + c0c * 16, QB + (size_t)r0c * 256 + kb + c0c * 8);
        cp_async16(bB + r1c * TPAD + c1c * 16, QB + (size_t)r1c * 256 + kb + c1c * 8);
        cp_async_commit();
    };

    const int m_off = (w & 1) * 64;
    const int n_off = (w >> 1) * 32;
    const int lrow = lane & 15;
    const int lseg = (lane >> 4) * 16;

    float acc[4][4][4] = {};

    load_chunk(0, 0); load_chunk(1, 1); load_chunk(2, 2);
    for (int ch = 0; ch < NSTEP; ch++) {
        if (ch <= NSTEP - 3) cp_async_wait<2>();
        else if (ch == NSTEP - 2) cp_async_wait<1>();
        else cp_async_wait<0>();
        __syncthreads();
        if (ch + 3 < NSTEP) load_chunk(ch + 3, (ch + 3) & 3);

        const uint32_t aB = aBase + (ch & 3) * TILE_BYTES;
        const uint32_t bB = bBase + (ch & 3) * TILE_BYTES;
#pragma unroll
        for (int kk = 0; kk < 2; kk++) {
            uint32_t afr[4][4];
#pragma unroll
            for (int mt = 0; mt < 4; mt++) {
                uint32_t addr = aB + (m_off + mt * 16 + lrow) * TPAD + kk * 32 + lseg;
                ldmatrix_x4(afr[mt][0], afr[mt][1], afr[mt][2], afr[mt][3], addr);
            }
            uint32_t bfr[4][2];
#pragma unroll
            for (int np = 0; np < 2; np++) {
                uint32_t q0, q1, q2, q3;
                uint32_t addr = bB + (n_off + np * 16 + lrow) * TPAD + kk * 32 + lseg;
                ldmatrix_x4(q0, q1, q2, q3, addr);
                bfr[np * 2][0] = q0; bfr[np * 2][1] = q2;
                bfr[np * 2 + 1][0] = q1; bfr[np * 2 + 1][1] = q3;
            }
#pragma unroll
            for (int mt = 0; mt < 4; mt++)
#pragma unroll
                for (int nt = 0; nt < 4; nt++)
                    mma_f16(acc[mt][nt], afr[mt], bfr[nt]);
        }
    }
    __syncthreads();

    // epilogue: bias, write fp16 proj, accumulate row stats (ss, dt) in fp32
    const int gr = lane >> 2, tig = lane & 3;
#pragma unroll
    for (int mt = 0; mt < 4; mt++) {
        const int r0l = m_off + mt * 16 + gr;
        const int r1l = r0l + 8;
        const size_t gr0 = (size_t)(i0 + r0l), gr1 = (size_t)(i0 + r1l);
        float ss0 = 0.f, dt0 = 0.f, ss1 = 0.f, dt1 = 0.f;
#pragma unroll
        for (int nt = 0; nt < 4; nt++) {
            const int cl = n_off + nt * 8 + tig * 2;
            float v00 = acc[mt][nt][0] + bsh[cl];
            float v01 = acc[mt][nt][1] + bsh[cl + 1];
            float v10 = acc[mt][nt][2] + bsh[cl];
            float v11 = acc[mt][nt][3] + bsh[cl + 1];
            *(__half2*)(g_qh + gr0 * 256 + e0 + cl) =
                __halves2half2(__float2half(v00), __float2half(v01));
            *(__half2*)(g_qh + gr1 * 256 + e0 + cl) =
                __halves2half2(__float2half(v10), __float2half(v11));
            const float w0 = wsm[cl], w1 = wsm[cl + 1];
            ss0 += v00 * v00 + v01 * v01;
            dt0 += v00 * w0 + v01 * w1;
            ss1 += v10 * v10 + v11 * v11;
            dt1 += v10 * w0 + v11 * w1;
        }
        ss0 += __shfl_xor_sync(0xffffffffu, ss0, 1);
        ss0 += __shfl_xor_sync(0xffffffffu, ss0, 2);
        dt0 += __shfl_xor_sync(0xffffffffu, dt0, 1);
        dt0 += __shfl_xor_sync(0xffffffffu, dt0, 2);
        ss1 += __shfl_xor_sync(0xffffffffu, ss1, 1);
        ss1 += __shfl_xor_sync(0xffffffffu, ss1, 2);
        dt1 += __shfl_xor_sync(0xffffffffu, dt1, 1);
        dt1 += __shfl_xor_sync(0xffffffffu, dt1, 2);
        if (tig == 0) {
            atomicAdd(&g_ss[gr0], ss0);
            atomicAdd(&g_dt[gr0], dt0);
            atomicAdd(&g_ss[gr1], ss1);
            atomicAdd(&g_dt[gr1], dt1);
        }
    }
}

// ---------------- K3: adj GEMM via warp fp16 mma.sync (K=256), symmetric -----------
__global__ void __launch_bounds__(256, 2) k_adj_mma(float* __restrict__ adj_out,
                                                    const float* __restrict__ bs) {
    extern __shared__ __align__(16) char dynsm[];
    char* smA = dynsm;
    char* smB = dynsm + NBUF * TILE_BYTES;
    float* aux = (float*)(dynsm + MMA_BUF_BYTES);
    float* rI = aux;          float* sI = aux + 128;   // sI/sM hold 0.5*sigmoid
    float* rM = aux + 256;    float* sM = aux + 384;
    float* sdeg = aux + 512;  float* sdegM = aux + 640;
    float* stage = (float*)dynsm;      // 128 x 132 fp32 = 67584 B, aliases MMA bufs

    const int tid = threadIdx.x;
    const int lane = tid & 31, w = tid >> 5;
    const int b = blockIdx.z;
    const float bs0 = bs[0];

    // map blockIdx.x (0..135) -> upper-triangle tile (ti, tj), ti<=tj, 16x16
    int ti = 0, rem = blockIdx.x;
    while (rem >= 16 - ti) { rem -= 16 - ti; ti++; }
    const int tj = ti + rem;
    const int i0 = ti * 128;
    const int m0 = tj * 128;
    const bool offdiag = (ti != tj);

    if (tid < 128) {
        int row = b * N + i0 + tid;
        rI[tid] = rsqrtf(fmaxf(g_ss[row], 1e-24f));
        sI[tid] = 0.5f / (1.0f + __expf(-(g_dt[row] + bs0)));
        sdeg[tid] = 0.f;
    } else {
        int t = tid - 128;
        int row = b * N + m0 + t;
        rM[t] = rsqrtf(fmaxf(g_ss[row], 1e-24f));
        sM[t] = 0.5f / (1.0f + __expf(-(g_dt[row] + bs0)));
        sdegM[t] = 0.f;
    }

    const __half* QA = g_qh + (size_t)(b * N + i0) * 256;
    const __half* QB = g_qh + (size_t)(b * N + m0) * 256;
    const uint32_t aBase = smem_to_u32(smA);
    const uint32_t bBase = smem_to_u32(smB);

    const int r0c = (tid + 0)   >> 2, c0c = (tid + 0)   & 3;
    const int r1c = (tid + 256) >> 2, c1c = (tid + 256) & 3;

    auto load_chunk = [&](int s, int buf) {
        int kb = s * 32;
        uint32_t aB = aBase + buf * TILE_BYTES;
        uint32_t bB = bBase + buf * TILE_BYTES;
        cp_async16(aB + r0c * TPAD + c0c * 16, QA + (size_t)r0c * 256 + kb + c0c * 8);
        cp_async16(aB + r1c * TPAD + c1c * 16, QA + (size_t)r1c * 256 + kb + c1c * 8);
        cp_async16(bB + r0c * TPAD + c0c * 16, QB + (size_t)r0c * 256 + kb + c0c * 8);
        cp_async16(bB + r1c * TPAD + c1c * 16, QB + (size_t)r1c * 256 + kb + c1c * 8);
        cp_async_commit();
    };

    const int m_off = (w & 1) * 64;
    const int n_off = (w >> 1) * 32;
    const int lrow = lane & 15;
    const int lseg = (lane >> 4) * 16;

    float acc[4][4][4] = {};

    load_chunk(0, 0); load_chunk(1, 1); load_chunk(2, 2);
    for (int ch = 0; ch < NSTEP; ch++) {
        if (ch <= NSTEP - 3) cp_async_wait<2>();
        else if (ch == NSTEP - 2) cp_async_wait<1>();
        else cp_async_wait<0>();
        __syncthreads();
        if (ch + 3 < NSTEP) load_chunk(ch + 3, (ch + 3) & 3);

        const uint32_t aB = aBase + (ch & 3) * TILE_BYTES;
        const uint32_t bB = bBase + (ch & 3) * TILE_BYTES;
#pragma unroll
        for (int kk = 0; kk < 2; kk++) {
            uint32_t afr[4][4];
#pragma unroll
            for (int mt = 0; mt < 4; mt++) {
                uint32_t addr = aB + (m_off + mt * 16 + lrow) * TPAD + kk * 32 + lseg;
                ldmatrix_x4(afr[mt][0], afr[mt][1], afr[mt][2], afr[mt][3], addr);
            }
            uint32_t bfr[4][2];
#pragma unroll
            for (int np = 0; np < 2; np++) {
                uint32_t q0, q1, q2, q3;
                uint32_t addr = bB + (n_off + np * 16 + lrow) * TPAD + kk * 32 + lseg;
                ldmatrix_x4(q0, q1, q2, q3, addr);
                bfr[np * 2][0] = q0; bfr[np * 2][1] = q2;
                bfr[np * 2 + 1][0] = q1; bfr[np * 2 + 1][1] = q3;
            }
#pragma unroll
            for (int mt = 0; mt < 4; mt++)
#pragma unroll
                for (int nt = 0; nt < 4; nt++)
                    mma_f16(acc[mt][nt], afr[mt], bfr[nt]);
        }
    }
    __syncthreads();   // MMA buffers dead; stage writes may begin

    // ---- epilogue: scale, clamp, write normal block, stage mirror, row/col sums --
    const int gr = lane >> 2, tig = lane & 3;
    float cs0[4] = {}, cs1[4] = {};
#pragma unroll
    for (int mt = 0; mt < 4; mt++) {
        const int r0l = m_off + mt * 16 + gr;
        const int r1l = r0l + 8;
        const float rn0 = rI[r0l], s0 = sI[r0l];
        const float rn1 = rI[r1l], s1 = sI[r1l];
        float* row0p = adj_out + ((size_t)(b * N + i0 + r0l)) * N + m0;
        float* row1p = adj_out + ((size_t)(b * N + i0 + r1l)) * N + m0;
        float d0 = 0.f, d1 = 0.f;
#pragma unroll
        for (int nt = 0; nt < 4; nt++) {
            const int cl = n_off + nt * 8 + tig * 2;
            const float rmA = rM[cl], rmB = rM[cl + 1];
            const float smA_ = sM[cl], smB_ = sM[cl + 1];
            float v00 = fmaxf(fminf(fmaxf(s0 + smA_, 1e-6f), 1.0f) *
                              (acc[mt][nt][0] * rn0 * rmA), 1e-6f);
            float v01 = fmaxf(fminf(fmaxf(s0 + smB_, 1e-6f), 1.0f) *
                              (acc[mt][nt][1] * rn0 * rmB), 1e-6f);
            float v10 = fmaxf(fminf(fmaxf(s1 + smA_, 1e-6f), 1.0f) *
                              (acc[mt][nt][2] * rn1 * rmA), 1e-6f);
            float v11 = fmaxf(fminf(fmaxf(s1 + smB_, 1e-6f), 1.0f) *
                              (acc[mt][nt][3] * rn1 * rmB), 1e-6f);
            d0 += v00 + v01;
            d1 += v10 + v11;
            cs0[nt] += v00 + v10;
            cs1[nt] += v01 + v11;
            *(float2*)(row0p + cl) = make_float2(v00, v01);
            *(float2*)(row1p + cl) = make_float2(v10, v11);
            if (offdiag) {
                stage[cl * 132 + r0l] = v00;
                stage[(cl + 1) * 132 + r0l] = v01;
                stage[cl * 132 + r1l] = v10;
                stage[(cl + 1) * 132 + r1l] = v11;
            }
        }
        d0 += __shfl_xor_sync(0xffffffffu, d0, 1);
        d0 += __shfl_xor_sync(0xffffffffu, d0, 2);
        d1 += __shfl_xor_sync(0xffffffffu, d1, 1);
        d1 += __shfl_xor_sync(0xffffffffu, d1, 2);
        if (tig == 0) {
            atomicAdd(&sdeg[r0l], d0);
            atomicAdd(&sdeg[r1l], d1);
        }
    }
    if (offdiag) {
#pragma unroll
        for (int nt = 0; nt < 4; nt++) {
            float c0 = cs0[nt], c1 = cs1[nt];
#pragma unroll
            for (int o = 4; o < 32; o <<= 1) {
                c0 += __shfl_xor_sync(0xffffffffu, c0, o);
                c1 += __shfl_xor_sync(0xffffffffu, c1, o);
            }
            if (lane < 4) {
                atomicAdd(&sdegM[n_off + nt * 8 + tig * 2], c0);
                atomicAdd(&sdegM[n_off + nt * 8 + tig * 2 + 1], c1);
            }
        }
    }
    __syncthreads();   // sdeg/sdegM and stage complete
    if (tid < 128) atomicAdd(&g_deg[b * N + i0 + tid], sdeg[tid]);
    if (offdiag && tid >= 128)
        atomicAdd(&g_deg[b * N + m0 + (tid - 128)], sdegM[tid - 128]);

    // ---- mirror drain: warp per row, streaming (evict-first) coalesced stores ----
    if (offdiag) {
#pragma unroll
        for (int rr = 0; rr < 16; rr++) {
            int row = rr * 8 + w;
            const float4* src = (const float4*)(stage + row * 132);
            float4* dst = (float4*)(adj_out + ((size_t)(b * N + m0 + row)) * N + i0);
            __stcs(dst + lane, src[lane]);     // mirror half is never re-read
        }
    }
}

// ---------------- K4: w via upper-triangle only; REVERSE order for L2 reuse --------
__global__ void k_wacc_tri(const float* __restrict__ adj) {
    __shared__ float rdI[128], rdJ[128], wcol[128], wrow[128];
    const int b = (B - 1) - blockIdx.y;               // LIFO vs k_adj write order
    int tidx = 135 - blockIdx.x;                      // freshest tiles first
    int ti = 0, rem = tidx;
    while (rem >= 16 - ti) { rem -= 16 - ti; ti++; }
    const int tj = ti + rem;
    const int i0 = ti * 128;
    const int m0 = tj * 128;
    const bool offdiag = (ti != tj);
    const int tid = threadIdx.x, lane = tid & 31, w = tid >> 5;

    if (tid < 128) {
        rdI[tid] = 1.0f / fmaxf(g_deg[b * N + i0 + tid], 1e-6f);
        wcol[tid] = 0.f;
    } else {
        int t = tid - 128;
        rdJ[t] = 1.0f / fmaxf(g_deg[b * N + m0 + t], 1e-6f);
        wrow[t] = 0.f;
    }
    __syncthreads();

    const float4 rj = *(const float4*)(rdJ + lane * 4);
    float colacc[4] = {};
#pragma unroll
    for (int rr = 0; rr < 16; rr++) {
        const int r = w * 16 + rr;
        const float4 a = __ldcs((const float4*)(adj +
                         ((size_t)(b * N + i0 + r)) * N + m0) + lane);
        const float rw = rdI[r];
        colacc[0] += a.x * rw; colacc[1] += a.y * rw;
        colacc[2] += a.z * rw; colacc[3] += a.w * rw;
        float rs = a.x * rj.x + a.y * rj.y + a.z * rj.z + a.w * rj.w;
#pragma unroll
        for (int o = 16; o > 0; o >>= 1) rs += __shfl_xor_sync(0xffffffffu, rs, o);
        if (lane == 0) wrow[r] = rs;
    }
#pragma unroll
    for (int k = 0; k < 4; k++) atomicAdd(&wcol[lane * 4 + k], colacc[k]);
    __syncthreads();
    if (tid < 128) atomicAdd(&g_w[b * N + m0 + tid], wcol[tid]);
    if (offdiag && tid >= 128)
        atomicAdd(&g_w[b * N + i0 + (tid - 128)], wrow[tid - 128]);
}

// ---------------- K6: rpart[c][b][d] = sum_{m in chunk} w[m]*proj16[b][m][d] ------
__global__ void k_rbar() {
    __shared__ float wS[64];
    const int b = blockIdx.y, m0 = blockIdx.x * 64, d = threadIdx.x;
    if (d < 64) wS[d] = g_w[b * N + m0 + d];
    __syncthreads();
    const __half* Q = g_qh + (size_t)(b * N + m0) * 256;
    float acc = 0.f;
#pragma unroll 8
    for (int m = 0; m < 64; m++)
        acc += __half2float(__ldcs(Q + m * 256 + d)) * wS[m];
    g_rpart[blockIdx.x * BD + b * D + d] = acc;
}

// ---------------- K7: final projections + LayerNorm -> out[b][d] ------------------
__global__ void k_final(const float* __restrict__ W_rp, const float* __restrict__ b_rp,
                        const float* __restrict__ W_gp, const float* __restrict__ b_gp,
                        const float* __restrict__ gamma, const float* __restrict__ beta,
                        float* __restrict__ out) {
    __shared__ float v[256];
    __shared__ float red[8];
    __shared__ float bcast;
    const int b = blockIdx.x, e = threadIdx.x;
    const int lane = e & 31, warp = e >> 5;

    float xs = 0.f, rb = 0.f;
#pragma unroll
    for (int c = 0; c < 32; c++) {
        xs += g_xpart[c * BD + b * D + e];
        rb += g_rpart[c * BD + b * D + e];
    }

    v[e] = rb * (1.0f / (float)N);
    __syncthreads();

    float g1 = b_rp[e];
#pragma unroll 4
    for (int d = 0; d < D; d++) g1 += v[d] * W_rp[d * D + e];
    __syncthreads();
    v[e] = g1;
    __syncthreads();

    float g2 = b_gp[e];
#pragma unroll 4
    for (int d = 0; d < D; d++) g2 += v[d] * W_gp[d * D + e];

    float h = g2 + xs * (1.0f / (float)N);

    float sum = h;
#pragma unroll
    for (int o = 16; o > 0; o >>= 1) sum += __shfl_xor_sync(0xffffffffu, sum, o);
    if (lane == 0) red[warp] = sum;
    __syncthreads();
    if (e == 0) {
        float s = 0.f;
        for (int i = 0; i < 8; i++) s += red[i];
        bcast = s * (1.0f / (float)D);
    }
    __syncthreads();
    float mu = bcast;
    float c = h - mu;
    float sq = c * c;
#pragma unroll
    for (int o = 16; o > 0; o >>= 1) sq += __shfl_xor_sync(0xffffffffu, sq, o);
    __syncthreads();
    if (lane == 0) red[warp] = sq;
    __syncthreads();
    if (e == 0) {
        float s = 0.f;
        for (int i = 0; i < 8; i++) s += red[i];
        bcast = s * (1.0f / (float)D);
    }
    __syncthreads();
    float var = bcast;
    out[b * D + e] = c * rsqrtf(var + 1e-5f) * gamma[e] + beta[e];
}

// ---------------- launch ----------------------------------------------------------
extern "C" void kernel_launch(void* const* d_in, const int* in_sizes, int n_in,
                              void* d_out, int out_size) {
    const float* x    = (const float*)d_in[0];
    const float* W_fp = (const float*)d_in[1];
    const float* b_fp = (const float*)d_in[2];
    const float* w_s  = (const float*)d_in[3];
    const float* b_s  = (const float*)d_in[4];
    const float* W_rp = (const float*)d_in[5];
    const float* b_rp = (const float*)d_in[6];
    const float* W_gp = (const float*)d_in[7];
    const float* b_gp = (const float*)d_in[8];
    const float* gamma= (const float*)d_in[9];
    const float* beta = (const float*)d_in[10];

    float* out = (float*)d_out;        // [B,1,D] = 2048 floats
    float* adj = out + B * D;          // [B,N,N] follows

    cudaFuncSetAttribute(k_adj_mma, cudaFuncAttributeMaxDynamicSharedMemorySize, ADJ_SMEM);
    cudaFuncSetAttribute(k_proj_mma, cudaFuncAttributeMaxDynamicSharedMemorySize, PROJ_SMEM);

    k_splitx<<<324, 256>>>(x, W_fp);
    k_proj_mma<<<dim3(BN / 128, 2), 256, PROJ_SMEM>>>(b_fp, w_s);
    k_adj_mma<<<dim3(136, 1, B), 256, ADJ_SMEM>>>(adj, b_s);
    k_wacc_tri<<<dim3(136, B), 256>>>(adj);
    k_rbar<<<dim3(N / 64, B), 256>>>();
    k_final<<<B, 256>>>(W_rp, b_rp, W_gp, b_gp, gamma, beta, out);
}

// round 15
// speedup vs baseline: 1.1776x; 1.1776x over previous
#include <cuda_runtime.h>
#include <cuda_bf16.h>
#include <cuda_fp16.h>
#include <math.h>
#include <cstdint>

// Problem constants
#define B 8
#define N 2048
#define D 256
#define BN (B*N)           // 16384 rows
#define BD (B*D)           // 2048

// ---------------- scratch (__device__ globals; no allocations allowed) ----------
__device__ __half g_qh[(size_t)BN * 256];         // 8.4 MB: fp16 of proj (adj GEMM input)
__device__ __half g_xq[(size_t)BN * 256];         // 8.4 MB: fp16 of x
__device__ __half g_wq[256 * 256];                // fp16 of W_fp^T (row e, col d)
__device__ float g_ss[BN];           // sum proj^2 per row (atomic)
__device__ float g_dt[BN];           // proj . w_s per row (atomic)
__device__ float g_deg[BN];          // row sums of adj (atomic)
__device__ float g_w[BN];            // w[m] = sum_i adj[m,i]/deg[i] (atomic)
__device__ float g_xpart[32 * BD];   // partial sums of x over n (32 chunks)
__device__ float g_rpart[32 * BD];   // partial sums of w*proj over m (32 chunks)
__device__ float g_Wc[256 * 256];    // W_rp @ W_gp (combined projection)
__device__ float g_bc[256];          // b_rp @ W_gp + b_gp

// ======================= helpers (arch-agnostic PTX only) ==========================
__device__ __forceinline__ uint32_t smem_to_u32(const void* smem_ptr) {
    uint32_t addr;
    asm("{ .reg .u64 tmp; cvta.to.shared.u64 tmp, %1; cvt.u32.u64 %0, tmp; }"
        : "=r"(addr) : "l"(smem_ptr));
    return addr;
}
template<int NG>
__device__ __forceinline__ void cp_async_wait() {
    asm volatile("cp.async.wait_group %0;" :: "n"(NG));
}
__device__ __forceinline__ void cp_async16(uint32_t dst, const void* src) {
    asm volatile("cp.async.cg.shared.global [%0], [%1], 16;" :: "r"(dst), "l"(src));
}
__device__ __forceinline__ void cp_async_commit() {
    asm volatile("cp.async.commit_group;" ::: "memory");
}
__device__ __forceinline__ void ldmatrix_x4(uint32_t& r0, uint32_t& r1,
                                            uint32_t& r2, uint32_t& r3, uint32_t addr) {
    asm volatile("ldmatrix.sync.aligned.m8n8.x4.shared.b16 {%0,%1,%2,%3}, [%4];"
                 : "=r"(r0), "=r"(r1), "=r"(r2), "=r"(r3) : "r"(addr));
}
__device__ __forceinline__ void mma_f16(float* c, const uint32_t* a, const uint32_t* b) {
    asm volatile(
        "mma.sync.aligned.m16n8k16.row.col.f32.f16.f16.f32 "
        "{%0,%1,%2,%3}, {%4,%5,%6,%7}, {%8,%9}, {%0,%1,%2,%3};"
        : "+f"(c[0]), "+f"(c[1]), "+f"(c[2]), "+f"(c[3])
        : "r"(a[0]), "r"(a[1]), "r"(a[2]), "r"(a[3]), "r"(b[0]), "r"(b[1]));
}

#define TPAD 80
#define TILE_BYTES (128 * TPAD)     // 10240
#define NBUF 4
#define NSTEP 8
#define MMA_BUF_BYTES (NBUF * TILE_BYTES * 2)      // 81920 (stage 128x132 fp32 fits)
#define ADJ_SMEM (MMA_BUF_BYTES + 6 * 128 * 4)     // + rI,sI,rM,sM,sdeg,sdegM
#define PROJ_SMEM (MMA_BUF_BYTES + 1024)           // + bias[128] + ws[128]

// ---------------- K-splitx: fp16 of x + xpart; fp16 W^T; zero; W_comb; b_comb ------
__global__ void k_splitx(const float* __restrict__ x, const float* __restrict__ W,
                         const float* __restrict__ W_rp, const float* __restrict__ W_gp,
                         const float* __restrict__ b_rp, const float* __restrict__ b_gp) {
    const int blk = blockIdx.x;
    const int d = threadIdx.x;
    if (blk < 256) {
        const int b = blk >> 5;            // 32 chunks per batch
        const int n0 = (blk & 31) * 64;
        const float* X = x + (size_t)(b * N + n0) * D;
        __half* Q = g_xq + (size_t)(b * N + n0) * 256;
        float acc = 0.f;
#pragma unroll 8
        for (int n = 0; n < 64; n++) {
            float v = X[n * D + d];
            acc += v;
            Q[n * 256 + d] = __float2half(v);
        }
        g_xpart[(blk & 31) * BD + b * D + d] = acc;
    } else if (blk < 260) {
        const int base = (blk - 256) * 16384;
        for (int i = 0; i < 64; i++) {
            int j = base + i * 256 + d;
            int e = j >> 8, dd = j & 255;
            g_wq[e * 256 + dd] = __float2half(W[dd * D + e]);
        }
    } else if (blk < 324) {
        int t = (blk - 260) * 256 + d;     // 64 blocks cover BN
        g_ss[t] = 0.f; g_dt[t] = 0.f; g_deg[t] = 0.f; g_w[t] = 0.f;
    } else if (blk < 356) {
        // W_comb rows d0..d0+7: Wc[dr][e] = sum_k W_rp[dr][k] * W_gp[k][e]
        __shared__ float wr[8][256];
        const int d0 = (blk - 324) * 8;
        for (int j = d; j < 8 * 256; j += 256)
            ((float*)wr)[j] = W_rp[d0 * 256 + j];
        __syncthreads();
        float acc[8] = {};
#pragma unroll 4
        for (int k = 0; k < 256; k++) {
            float g = W_gp[k * 256 + d];
#pragma unroll
            for (int j = 0; j < 8; j++) acc[j] += wr[j][k] * g;
        }
#pragma unroll
        for (int j = 0; j < 8; j++) g_Wc[(d0 + j) * 256 + d] = acc[j];
    } else {
        // bias_comb[e] = sum_k b_rp[k] * W_gp[k][e] + b_gp[e]
        float acc = b_gp[d];
#pragma unroll 4
        for (int k = 0; k < 256; k++) acc += b_rp[k] * W_gp[k * 256 + d];
        g_bc[d] = acc;
    }
}

// ---------------- K1: proj GEMM on tensor cores (fp16, K=256) + row stats ----------
__global__ void __launch_bounds__(256, 2) k_proj_mma(const float* __restrict__ bias,
                                                     const float* __restrict__ ws) {
    extern __shared__ __align__(16) char dynsm[];
    char* smA = dynsm;
    char* smB = dynsm + NBUF * TILE_BYTES;
    float* bsh = (float*)(dynsm + MMA_BUF_BYTES);
    float* wsm = bsh + 128;

    const int tid = threadIdx.x;
    const int lane = tid & 31, w = tid >> 5;
    const int i0 = blockIdx.x * 128;
    const int e0 = blockIdx.y * 128;

    if (tid < 128) { bsh[tid] = bias[e0 + tid]; wsm[tid] = ws[e0 + tid]; }

    const __half* QA = g_xq + (size_t)i0 * 256;
    const __half* QB = g_wq + (size_t)e0 * 256;
    const uint32_t aBase = smem_to_u32(smA);
    const uint32_t bBase = smem_to_u32(smB);

    const int r0c = (tid + 0)   >> 2, c0c = (tid + 0)   & 3;
    const int r1c = (tid + 256) >> 2, c1c = (tid + 256) & 3;

    auto load_chunk = [&](int s, int buf) {
        int kb = s * 32;
        uint32_t aB = aBase + buf * TILE_BYTES;
        uint32_t bB = bBase + buf * TILE_BYTES;
        cp_async16(aB + r0c * TPAD + c0c * 16, QA + (size_t)r0c * 256 + kb + c0c * 8);
        cp_async16(aB + r1c * TPAD + c1c * 16, QA + (size_t)r1c * 256 + kb + c1c * 8);
        cp_async16(bB + r0c * TPAD + c0c * 16, QB + (size_t)r0c * 256 + kb + c0c * 8);
        cp_async16(bB + r1c * TPAD + c1c * 16, QB + (size_t)r1c * 256 + kb + c1c * 8);
        cp_async_commit();
    };

    const int m_off = (w & 1) * 64;
    const int n_off = (w >> 1) * 32;
    const int lrow = lane & 15;
    const int lseg = (lane >> 4) * 16;

    float acc[4][4][4] = {};

    load_chunk(0, 0); load_chunk(1, 1); load_chunk(2, 2);
    for (int ch = 0; ch < NSTEP; ch++) {
        if (ch <= NSTEP - 3) cp_async_wait<2>();
        else if (ch == NSTEP - 2) cp_async_wait<1>();
        else cp_async_wait<0>();
        __syncthreads();
        if (ch + 3 < NSTEP) load_chunk(ch + 3, (ch + 3) & 3);

        const uint32_t aB = aBase + (ch & 3) * TILE_BYTES;
        const uint32_t bB = bBase + (ch & 3) * TILE_BYTES;
#pragma unroll
        for (int kk = 0; kk < 2; kk++) {
            uint32_t afr[4][4];
#pragma unroll
            for (int mt = 0; mt < 4; mt++) {
                uint32_t addr = aB + (m_off + mt * 16 + lrow) * TPAD + kk * 32 + lseg;
                ldmatrix_x4(afr[mt][0], afr[mt][1], afr[mt][2], afr[mt][3], addr);
            }
            uint32_t bfr[4][2];
#pragma unroll
            for (int np = 0; np < 2; np++) {
                uint32_t q0, q1, q2, q3;
                uint32_t addr = bB + (n_off + np * 16 + lrow) * TPAD + kk * 32 + lseg;
                ldmatrix_x4(q0, q1, q2, q3, addr);
                bfr[np * 2][0] = q0; bfr[np * 2][1] = q2;
                bfr[np * 2 + 1][0] = q1; bfr[np * 2 + 1][1] = q3;
            }
#pragma unroll
            for (int mt = 0; mt < 4; mt++)
#pragma unroll
                for (int nt = 0; nt < 4; nt++)
                    mma_f16(acc[mt][nt], afr[mt], bfr[nt]);
        }
    }
    __syncthreads();

    // epilogue: bias, write fp16 proj, accumulate row stats (ss, dt) in fp32
    const int gr = lane >> 2, tig = lane & 3;
#pragma unroll
    for (int mt = 0; mt < 4; mt++) {
        const int r0l = m_off + mt * 16 + gr;
        const int r1l = r0l + 8;
        const size_t gr0 = (size_t)(i0 + r0l), gr1 = (size_t)(i0 + r1l);
        float ss0 = 0.f, dt0 = 0.f, ss1 = 0.f, dt1 = 0.f;
#pragma unroll
        for (int nt = 0; nt < 4; nt++) {
            const int cl = n_off + nt * 8 + tig * 2;
            float v00 = acc[mt][nt][0] + bsh[cl];
            float v01 = acc[mt][nt][1] + bsh[cl + 1];
            float v10 = acc[mt][nt][2] + bsh[cl];
            float v11 = acc[mt][nt][3] + bsh[cl + 1];
            *(__half2*)(g_qh + gr0 * 256 + e0 + cl) =
                __halves2half2(__float2half(v00), __float2half(v01));
            *(__half2*)(g_qh + gr1 * 256 + e0 + cl) =
                __halves2half2(__float2half(v10), __float2half(v11));
            const float w0 = wsm[cl], w1 = wsm[cl + 1];
            ss0 += v00 * v00 + v01 * v01;
            dt0 += v00 * w0 + v01 * w1;
            ss1 += v10 * v10 + v11 * v11;
            dt1 += v10 * w0 + v11 * w1;
        }
        ss0 += __shfl_xor_sync(0xffffffffu, ss0, 1);
        ss0 += __shfl_xor_sync(0xffffffffu, ss0, 2);
        dt0 += __shfl_xor_sync(0xffffffffu, dt0, 1);
        dt0 += __shfl_xor_sync(0xffffffffu, dt0, 2);
        ss1 += __shfl_xor_sync(0xffffffffu, ss1, 1);
        ss1 += __shfl_xor_sync(0xffffffffu, ss1, 2);
        dt1 += __shfl_xor_sync(0xffffffffu, dt1, 1);
        dt1 += __shfl_xor_sync(0xffffffffu, dt1, 2);
        if (tig == 0) {
            atomicAdd(&g_ss[gr0], ss0);
            atomicAdd(&g_dt[gr0], dt0);
            atomicAdd(&g_ss[gr1], ss1);
            atomicAdd(&g_dt[gr1], dt1);
        }
    }
}

// ---------------- K3: adj GEMM via warp fp16 mma.sync (K=256), symmetric -----------
__global__ void __launch_bounds__(256, 2) k_adj_mma(float* __restrict__ adj_out,
                                                    const float* __restrict__ bs) {
    extern __shared__ __align__(16) char dynsm[];
    char* smA = dynsm;
    char* smB = dynsm + NBUF * TILE_BYTES;
    float* aux = (float*)(dynsm + MMA_BUF_BYTES);
    float* rI = aux;          float* sI = aux + 128;   // sI/sM hold 0.5*sigmoid
    float* rM = aux + 256;    float* sM = aux + 384;
    float* sdeg = aux + 512;  float* sdegM = aux + 640;
    float* stage = (float*)dynsm;      // 128 x 132 fp32 = 67584 B, aliases MMA bufs

    const int tid = threadIdx.x;
    const int lane = tid & 31, w = tid >> 5;
    const int b = blockIdx.z;
    const float bs0 = bs[0];

    // map blockIdx.x (0..135) -> upper-triangle tile (ti, tj), ti<=tj, 16x16
    int ti = 0, rem = blockIdx.x;
    while (rem >= 16 - ti) { rem -= 16 - ti; ti++; }
    const int tj = ti + rem;
    const int i0 = ti * 128;
    const int m0 = tj * 128;
    const bool offdiag = (ti != tj);

    if (tid < 128) {
        int row = b * N + i0 + tid;
        rI[tid] = rsqrtf(fmaxf(g_ss[row], 1e-24f));
        sI[tid] = 0.5f / (1.0f + __expf(-(g_dt[row] + bs0)));
        sdeg[tid] = 0.f;
    } else {
        int t = tid - 128;
        int row = b * N + m0 + t;
        rM[t] = rsqrtf(fmaxf(g_ss[row], 1e-24f));
        sM[t] = 0.5f / (1.0f + __expf(-(g_dt[row] + bs0)));
        sdegM[t] = 0.f;
    }

    const __half* QA = g_qh + (size_t)(b * N + i0) * 256;
    const __half* QB = g_qh + (size_t)(b * N + m0) * 256;
    const uint32_t aBase = smem_to_u32(smA);
    const uint32_t bBase = smem_to_u32(smB);

    const int r0c = (tid + 0)   >> 2, c0c = (tid + 0)   & 3;
    const int r1c = (tid + 256) >> 2, c1c = (tid + 256) & 3;

    auto load_chunk = [&](int s, int buf) {
        int kb = s * 32;
        uint32_t aB = aBase + buf * TILE_BYTES;
        uint32_t bB = bBase + buf * TILE_BYTES;
        cp_async16(aB + r0c * TPAD + c0c * 16, QA + (size_t)r0c * 256 + kb + c0c * 8);
        cp_async16(aB + r1c * TPAD + c1c * 16, QA + (size_t)r1c * 256 + kb + c1c * 8);
        cp_async16(bB + r0c * TPAD + c0c * 16, QB + (size_t)r0c * 256 + kb + c0c * 8);
        cp_async16(bB + r1c * TPAD + c1c * 16, QB + (size_t)r1c * 256 + kb + c1c * 8);
        cp_async_commit();
    };

    const int m_off = (w & 1) * 64;
    const int n_off = (w >> 1) * 32;
    const int lrow = lane & 15;
    const int lseg = (lane >> 4) * 16;

    float acc[4][4][4] = {};

    load_chunk(0, 0); load_chunk(1, 1); load_chunk(2, 2);
    for (int ch = 0; ch < NSTEP; ch++) {
        if (ch <= NSTEP - 3) cp_async_wait<2>();
        else if (ch == NSTEP - 2) cp_async_wait<1>();
        else cp_async_wait<0>();
        __syncthreads();
        if (ch + 3 < NSTEP) load_chunk(ch + 3, (ch + 3) & 3);

        const uint32_t aB = aBase + (ch & 3) * TILE_BYTES;
        const uint32_t bB = bBase + (ch & 3) * TILE_BYTES;
#pragma unroll
        for (int kk = 0; kk < 2; kk++) {
            uint32_t afr[4][4];
#pragma unroll
            for (int mt = 0; mt < 4; mt++) {
                uint32_t addr = aB + (m_off + mt * 16 + lrow) * TPAD + kk * 32 + lseg;
                ldmatrix_x4(afr[mt][0], afr[mt][1], afr[mt][2], afr[mt][3], addr);
            }
            uint32_t bfr[4][2];
#pragma unroll
            for (int np = 0; np < 2; np++) {
                uint32_t q0, q1, q2, q3;
                uint32_t addr = bB + (n_off + np * 16 + lrow) * TPAD + kk * 32 + lseg;
                ldmatrix_x4(q0, q1, q2, q3, addr);
                bfr[np * 2][0] = q0; bfr[np * 2][1] = q2;
                bfr[np * 2 + 1][0] = q1; bfr[np * 2 + 1][1] = q3;
            }
#pragma unroll
            for (int mt = 0; mt < 4; mt++)
#pragma unroll
                for (int nt = 0; nt < 4; nt++)
                    mma_f16(acc[mt][nt], afr[mt], bfr[nt]);
        }
    }
    __syncthreads();   // MMA buffers dead; stage writes may begin

    // ---- epilogue: scale, clamp, write normal block, stage mirror, row/col sums --
    const int gr = lane >> 2, tig = lane & 3;
    float cs0[4] = {}, cs1[4] = {};
#pragma unroll
    for (int mt = 0; mt < 4; mt++) {
        const int r0l = m_off + mt * 16 + gr;
        const int r1l = r0l + 8;
        const float rn0 = rI[r0l], s0 = sI[r0l];
        const float rn1 = rI[r1l], s1 = sI[r1l];
        float* row0p = adj_out + ((size_t)(b * N + i0 + r0l)) * N + m0;
        float* row1p = adj_out + ((size_t)(b * N + i0 + r1l)) * N + m0;
        float d0 = 0.f, d1 = 0.f;
#pragma unroll
        for (int nt = 0; nt < 4; nt++) {
            const int cl = n_off + nt * 8 + tig * 2;
            const float rmA = rM[cl], rmB = rM[cl + 1];
            const float smA_ = sM[cl], smB_ = sM[cl + 1];
            float v00 = fmaxf(fminf(fmaxf(s0 + smA_, 1e-6f), 1.0f) *
                              (acc[mt][nt][0] * rn0 * rmA), 1e-6f);
            float v01 = fmaxf(fminf(fmaxf(s0 + smB_, 1e-6f), 1.0f) *
                              (acc[mt][nt][1] * rn0 * rmB), 1e-6f);
            float v10 = fmaxf(fminf(fmaxf(s1 + smA_, 1e-6f), 1.0f) *
                              (acc[mt][nt][2] * rn1 * rmA), 1e-6f);
            float v11 = fmaxf(fminf(fmaxf(s1 + smB_, 1e-6f), 1.0f) *
                              (acc[mt][nt][3] * rn1 * rmB), 1e-6f);
            d0 += v00 + v01;
            d1 += v10 + v11;
            cs0[nt] += v00 + v10;
            cs1[nt] += v01 + v11;
            *(float2*)(row0p + cl) = make_float2(v00, v01);
            *(float2*)(row1p + cl) = make_float2(v10, v11);
            if (offdiag) {
                stage[cl * 132 + r0l] = v00;
                stage[(cl + 1) * 132 + r0l] = v01;
                stage[cl * 132 + r1l] = v10;
                stage[(cl + 1) * 132 + r1l] = v11;
            }
        }
        d0 += __shfl_xor_sync(0xffffffffu, d0, 1);
        d0 += __shfl_xor_sync(0xffffffffu, d0, 2);
        d1 += __shfl_xor_sync(0xffffffffu, d1, 1);
        d1 += __shfl_xor_sync(0xffffffffu, d1, 2);
        if (tig == 0) {
            atomicAdd(&sdeg[r0l], d0);
            atomicAdd(&sdeg[r1l], d1);
        }
    }
    if (offdiag) {
#pragma unroll
        for (int nt = 0; nt < 4; nt++) {
            float c0 = cs0[nt], c1 = cs1[nt];
#pragma unroll
            for (int o = 4; o < 32; o <<= 1) {
                c0 += __shfl_xor_sync(0xffffffffu, c0, o);
                c1 += __shfl_xor_sync(0xffffffffu, c1, o);
            }
            if (lane < 4) {
                atomicAdd(&sdegM[n_off + nt * 8 + tig * 2], c0);
                atomicAdd(&sdegM[n_off + nt * 8 + tig * 2 + 1], c1);
            }
        }
    }
    __syncthreads();   // sdeg/sdegM and stage complete
    if (tid < 128) atomicAdd(&g_deg[b * N + i0 + tid], sdeg[tid]);
    if (offdiag && tid >= 128)
        atomicAdd(&g_deg[b * N + m0 + (tid - 128)], sdegM[tid - 128]);

    // ---- mirror drain: warp per row, streaming (evict-first) coalesced stores ----
    if (offdiag) {
#pragma unroll
        for (int rr = 0; rr < 16; rr++) {
            int row = rr * 8 + w;
            const float4* src = (const float4*)(stage + row * 132);
            float4* dst = (float4*)(adj_out + ((size_t)(b * N + m0 + row)) * N + i0);
            __stcs(dst + lane, src[lane]);     // mirror half is never re-read
        }
    }
}

// ---------------- K4: w via upper-triangle only (symmetry) ------------------------
__global__ void k_wacc_tri(const float* __restrict__ adj) {
    __shared__ float rdI[128], rdJ[128], wcol[128], wrow[128];
    const int b = blockIdx.y;
    int ti = 0, rem = blockIdx.x;
    while (rem >= 16 - ti) { rem -= 16 - ti; ti++; }
    const int tj = ti + rem;
    const int i0 = ti * 128;
    const int m0 = tj * 128;
    const bool offdiag = (ti != tj);
    const int tid = threadIdx.x, lane = tid & 31, w = tid >> 5;

    if (tid < 128) {
        rdI[tid] = 1.0f / fmaxf(g_deg[b * N + i0 + tid], 1e-6f);
        wcol[tid] = 0.f;
    } else {
        int t = tid - 128;
        rdJ[t] = 1.0f / fmaxf(g_deg[b * N + m0 + t], 1e-6f);
        wrow[t] = 0.f;
    }
    __syncthreads();

    const float4 rj = *(const float4*)(rdJ + lane * 4);
    float colacc[4] = {};
#pragma unroll
    for (int rr = 0; rr < 16; rr++) {
        const int r = w * 16 + rr;
        const float4 a = __ldcs((const float4*)(adj +
                         ((size_t)(b * N + i0 + r)) * N + m0) + lane);
        const float rw = rdI[r];
        colacc[0] += a.x * rw; colacc[1] += a.y * rw;
        colacc[2] += a.z * rw; colacc[3] += a.w * rw;
        float rs = a.x * rj.x + a.y * rj.y + a.z * rj.z + a.w * rj.w;
#pragma unroll
        for (int o = 16; o > 0; o >>= 1) rs += __shfl_xor_sync(0xffffffffu, rs, o);
        if (lane == 0) wrow[r] = rs;
    }
#pragma unroll
    for (int k = 0; k < 4; k++) atomicAdd(&wcol[lane * 4 + k], colacc[k]);
    __syncthreads();
    if (tid < 128) atomicAdd(&g_w[b * N + m0 + tid], wcol[tid]);
    if (offdiag && tid >= 128)
        atomicAdd(&g_w[b * N + i0 + (tid - 128)], wrow[tid - 128]);
}

// ---------------- K6: rpart[c][b][d] = sum_{m in chunk} w[m]*proj16[b][m][d] ------
__global__ void k_rbar() {
    __shared__ float wS[64];
    const int b = blockIdx.y, m0 = blockIdx.x * 64, d = threadIdx.x;
    if (d < 64) wS[d] = g_w[b * N + m0 + d];
    __syncthreads();
    const __half* Q = g_qh + (size_t)(b * N + m0) * 256;
    float acc = 0.f;
#pragma unroll 8
    for (int m = 0; m < 64; m++)
        acc += __half2float(__ldcs(Q + m * 256 + d)) * wS[m];
    g_rpart[blockIdx.x * BD + b * D + d] = acc;
}

// ---------------- K7: single combined GEMV + LayerNorm -> out[b][d] ---------------
__global__ void k_final(const float* __restrict__ gamma, const float* __restrict__ beta,
                        float* __restrict__ out) {
    __shared__ float v[256];
    __shared__ float red[8];
    __shared__ float bcast;
    const int b = blockIdx.x, e = threadIdx.x;
    const int lane = e & 31, warp = e >> 5;

    float xs = 0.f, rb = 0.f;
#pragma unroll
    for (int c = 0; c < 32; c++) {
        xs += g_xpart[c * BD + b * D + e];
        rb += g_rpart[c * BD + b * D + e];
    }

    v[e] = rb * (1.0f / (float)N);
    __syncthreads();

    // h = rbar_mean @ Wc + bc + xs_mean
    float g2 = g_bc[e];
#pragma unroll 8
    for (int d = 0; d < D; d++) g2 += v[d] * g_Wc[d * D + e];

    float h = g2 + xs * (1.0f / (float)N);

    float sum = h;
#pragma unroll
    for (int o = 16; o > 0; o >>= 1) sum += __shfl_xor_sync(0xffffffffu, sum, o);
    if (lane == 0) red[warp] = sum;
    __syncthreads();
    if (e == 0) {
        float s = 0.f;
        for (int i = 0; i < 8; i++) s += red[i];
        bcast = s * (1.0f / (float)D);
    }
    __syncthreads();
    float mu = bcast;
    float c = h - mu;
    float sq = c * c;
#pragma unroll
    for (int o = 16; o > 0; o >>= 1) sq += __shfl_xor_sync(0xffffffffu, sq, o);
    __syncthreads();
    if (lane == 0) red[warp] = sq;
    __syncthreads();
    if (e == 0) {
        float s = 0.f;
        for (int i = 0; i < 8; i++) s += red[i];
        bcast = s * (1.0f / (float)D);
    }
    __syncthreads();
    float var = bcast;
    out[b * D + e] = c * rsqrtf(var + 1e-5f) * gamma[e] + beta[e];
}

// ---------------- launch ----------------------------------------------------------
extern "C" void kernel_launch(void* const* d_in, const int* in_sizes, int n_in,
                              void* d_out, int out_size) {
    const float* x    = (const float*)d_in[0];
    const float* W_fp = (const float*)d_in[1];
    const float* b_fp = (const float*)d_in[2];
    const float* w_s  = (const float*)d_in[3];
    const float* b_s  = (const float*)d_in[4];
    const float* W_rp = (const float*)d_in[5];
    const float* b_rp = (const float*)d_in[6];
    const float* W_gp = (const float*)d_in[7];
    const float* b_gp = (const float*)d_in[8];
    const float* gamma= (const float*)d_in[9];
    const float* beta = (const float*)d_in[10];

    float* out = (float*)d_out;        // [B,1,D] = 2048 floats
    float* adj = out + B * D;          // [B,N,N] follows

    cudaFuncSetAttribute(k_adj_mma, cudaFuncAttributeMaxDynamicSharedMemorySize, ADJ_SMEM);
    cudaFuncSetAttribute(k_proj_mma, cudaFuncAttributeMaxDynamicSharedMemorySize, PROJ_SMEM);

    k_splitx<<<357, 256>>>(x, W_fp, W_rp, W_gp, b_rp, b_gp);
    k_proj_mma<<<dim3(BN / 128, 2), 256, PROJ_SMEM>>>(b_fp, w_s);
    k_adj_mma<<<dim3(136, 1, B), 256, ADJ_SMEM>>>(adj, b_s);
    k_wacc_tri<<<dim3(136, B), 256>>>(adj);
    k_rbar<<<dim3(N / 64, B), 256>>>();
    k_final<<<B, 256>>>(gamma, beta, out);
}